// round 15
// baseline (speedup 1.0000x reference)
#include <cuda_runtime.h>
#include <cuda_fp16.h>
#include <cstdint>

// ---------------- problem constants ----------------
#define BATCH   128
#define DIM     384
#define RES     14
#define NPIX    196
#define HEADS   8
#define KD      32
#define DV      128
#define DH      1024
#define OCQKV   1536
#define SCALE_ATTN 0.17677669529663687f
#define QT      16
#define QTILES  13
#define SP      208        // S row stride (floats) in attn smem
#define PST     105        // P half2 row stride (words) in attn smem
#define WST     20         // gemm smem W row stride (words)
#define XST     136        // gemm smem X row stride (words), 136 % 32 = 8 -> conflict-free
#define NBUF    3          // gemm pipeline depth
#define GEMM_SMEM ((NBUF * 128 * WST + NBUF * 16 * XST) * 4)

// ---------------- device scratch (16B-aligned for cp.async / vector access) ----------------
__device__ __align__(16) __half   g_wqkv [OCQKV * DIM];
__device__ float    g_bqkv [OCQKV];
__device__ __align__(16) __half   g_wproj[DIM * DH];
__device__ float    g_bproj[DIM];
__device__ float    g_wvl  [DH * 9];
__device__ float    g_bvl  [DH];
__device__ float    g_bias [HEADS * NPIX * NPIX];
__device__ __align__(16) uint32_t g_xp32 [(size_t)BATCH * 192 * NPIX];     // x half2-pairs [b][cpair][n]
__device__ __align__(16) uint32_t g_qp32 [(size_t)BATCH * 128 * 208];      // Q [b][cpair][n(208)]
__device__ __align__(16) uint32_t g_kp32 [(size_t)BATCH * 128 * 208];      // K [b][cpair][n(208)]
__device__ __align__(16) uint32_t g_vp32 [(size_t)BATCH * 104 * DH];       // V [b][mpair(104)][ch]
__device__ __align__(16) float    g_vf   [(size_t)BATCH * DH * NPIX];      // V float (vloc input)
__device__ __align__(16) __half   g_vlh  [(size_t)BATCH * 512 * NPIX * 2]; // vloc half paired [b][chpair][n][2]
__device__ __align__(16) uint32_t g_xop32[(size_t)BATCH * 512 * NPIX];     // xout half2 [b][chpair][n]

// ---------------- helpers ----------------
__device__ __forceinline__ uint32_t packh2(float lo, float hi) {
    __half2 h = __floats2half2_rn(lo, hi);
    return *(uint32_t*)&h;
}
__device__ __forceinline__ void mma16(float* c, uint32_t a0, uint32_t a1, uint32_t a2, uint32_t a3,
                                      uint32_t b0, uint32_t b1) {
    asm volatile(
        "mma.sync.aligned.m16n8k16.row.col.f32.f16.f16.f32 "
        "{%0,%1,%2,%3},{%4,%5,%6,%7},{%8,%9},{%0,%1,%2,%3};"
        : "+f"(c[0]), "+f"(c[1]), "+f"(c[2]), "+f"(c[3])
        : "r"(a0), "r"(a1), "r"(a2), "r"(a3), "r"(b0), "r"(b1));
}
__device__ __forceinline__ void cp16(uint32_t smem_dst, const void* gsrc) {
    asm volatile("cp.async.cg.shared.global [%0], [%1], 16;" :: "r"(smem_dst), "l"(gsrc));
}
#define CP_COMMIT()  asm volatile("cp.async.commit_group;")
#define CP_WAIT(n)   asm volatile("cp.async.wait_group %0;" :: "n"(n))

// ---------------- unified prep kernel (fold + bias + x-prep + pad) ----------------
#define SEG_A (OCQKV * DIM)                 // fold qkv weights
#define SEG_B (DIM * DH)                    // fold proj weights
#define SEG_C (DH * 9)                      // fold vl weights
#define SEG_D (HEADS * NPIX * NPIX)         // bias expand
#define SEG_E (BATCH * 192 * NPIX)          // x half2 pack
#define SEG_F (BATCH * 9216)                // pad zero q/k/v
#define PREP_TOTAL (SEG_A + SEG_B + SEG_C + SEG_D + SEG_E + SEG_F)

__global__ void prep_kernel(
    const float* __restrict__ x,
    const float* __restrict__ q_w, const float* __restrict__ q_b,
    const float* __restrict__ q_s, const float* __restrict__ q_t,
    const float* __restrict__ k_w, const float* __restrict__ k_b,
    const float* __restrict__ k_s, const float* __restrict__ k_t,
    const float* __restrict__ v_w, const float* __restrict__ v_b,
    const float* __restrict__ v_s, const float* __restrict__ v_t,
    const float* __restrict__ vl_w, const float* __restrict__ vl_b,
    const float* __restrict__ vl_s, const float* __restrict__ vl_t,
    const float* __restrict__ p_w, const float* __restrict__ p_b,
    const float* __restrict__ p_s, const float* __restrict__ p_t,
    const float* __restrict__ bias_seg, const int* __restrict__ bias_idxs,
    int n_off)
{
    int idx = blockIdx.x * blockDim.x + threadIdx.x;
    if (idx < SEG_A) {
        int oc = idx / DIM, c = idx - oc * DIM;
        float w, s;
        if (oc < 256) {
            w = q_w[oc * DIM + c]; s = q_s[oc] * SCALE_ATTN;
            if (c == 0) g_bqkv[oc] = (q_b[oc] * q_s[oc] + q_t[oc]) * SCALE_ATTN;
        } else if (oc < 512) {
            int o = oc - 256;
            w = k_w[o * DIM + c]; s = k_s[o];
            if (c == 0) g_bqkv[oc] = k_b[o] * k_s[o] + k_t[o];
        } else {
            int o = oc - 512;
            w = v_w[o * DIM + c]; s = v_s[o];
            if (c == 0) g_bqkv[oc] = v_b[o] * v_s[o] + v_t[o];
        }
        g_wqkv[idx] = __float2half_rn(w * s);
        return;
    }
    idx -= SEG_A;
    if (idx < SEG_B) {
        int oc = idx / DH;
        g_wproj[idx] = __float2half_rn(p_w[idx] * p_s[oc]);
        if ((idx - oc * DH) == 0) g_bproj[oc] = p_b[oc] * p_s[oc] + p_t[oc];
        return;
    }
    idx -= SEG_B;
    if (idx < SEG_C) {
        int ch = idx / 9;
        g_wvl[idx] = vl_w[idx] * vl_s[ch];
        if (idx == ch * 9) g_bvl[ch] = vl_b[ch] * vl_s[ch] + vl_t[ch];
        return;
    }
    idx -= SEG_C;
    if (idx < SEG_D) {
        int h = idx / (NPIX * NPIX), nm = idx - h * (NPIX * NPIX);
        g_bias[idx] = bias_seg[h * n_off + bias_idxs[nm]];
        return;
    }
    idx -= SEG_D;
    if (idx < SEG_E) {
        int n = idx % NPIX, cp = (idx / NPIX) % 192, b = idx / (NPIX * 192);
        const float* xr = x + ((size_t)b * DIM + 2 * cp) * NPIX + n;
        g_xp32[idx] = packh2(xr[0], xr[NPIX]);
        return;
    }
    idx -= SEG_E;
    if (idx < SEG_F) {
        int b = idx / 9216, i = idx % 9216;
        if (i < 1536) {
            int cp = i / 12, ni = i % 12;
            g_qp32[((size_t)b * 128 + cp) * 208 + 196 + ni] = 0u;
        } else if (i < 3072) {
            int r = i - 1536, cp = r / 12, ni = r % 12;
            g_kp32[((size_t)b * 128 + cp) * 208 + 196 + ni] = 0u;
        } else {
            int r = i - 3072;
            int mp = 98 + r / DH, d = r % DH;
            g_vp32[(size_t)b * 104 * DH + (size_t)mp * DH + d] = 0u;
        }
    }
}

// ---------------- fp16 GEMM: 256-thread CTA, tile 128oc x 104n, 2 CTAs/SM, 3-stage ----------------
__device__ __forceinline__ void gemm_stage(const __half* W, int ldw, const uint32_t* Xp,
                                           int oc0, int nh, int it, int buf,
                                           uint32_t sWb, uint32_t sXb, int tid)
{
    int k0 = it * 32;
    #pragma unroll
    for (int e = tid; e < 512; e += 256) {
        int oc = e >> 2, cc = e & 3;
        cp16(sWb + (((buf * 128) + oc) * WST + cc * 4) * 4,
             W + (size_t)(oc0 + oc) * ldw + k0 + cc * 8);
    }
    int cnt = nh ? 23 : 26;                 // nh1: cols 92..103 are global pad (prezeroed in smem)
    for (int e = tid; e < 16 * cnt; e += 256) {
        int pr = e / cnt, cc = e - pr * cnt;
        cp16(sXb + ((buf * 16 + pr) * XST + cc * 4) * 4,
             Xp + (size_t)(it * 16 + pr) * NPIX + nh * 104 + cc * 4);
    }
    CP_COMMIT();
}

// MODE 0: QKV (K=DIM, X=g_xp32), MODE 1: proj (K=DH, X=g_xop32, Y=d_out)
template<int MODE>
__global__ __launch_bounds__(256, 2)
void gemm_mma(float* __restrict__ Yout)
{
    extern __shared__ __align__(16) uint32_t dsm[];
    uint32_t* sW32 = dsm;                        // [NBUF][128][WST]
    uint32_t* sX32 = dsm + NBUF * 128 * WST;     // [NBUF][16][XST]

    const int K = (MODE == 0) ? DIM : DH;
    const __half* Wh = (MODE == 0) ? g_wqkv : g_wproj;
    const int b = blockIdx.x, oc0 = blockIdx.y * 128, nh = blockIdx.z;
    const uint32_t* Xp = ((MODE == 0) ? g_xp32 : g_xop32) + (size_t)b * (K / 2) * NPIX;

    const int tid = threadIdx.x, lane = tid & 31, w = tid >> 5;
    const int g = lane >> 2, q = lane & 3;
    const int ob = w * 16;

    if (nh) {
        for (int e = tid; e < NBUF * 16 * 12; e += 256) {
            int buf = e / 192, rem = e % 192;
            sX32[(buf * 16 + rem / 12) * XST + 92 + rem % 12] = 0u;
        }
        __syncthreads();
    }

    uint32_t sWb = (uint32_t)__cvta_generic_to_shared(sW32);
    uint32_t sXb = (uint32_t)__cvta_generic_to_shared(sX32);

    float c[13][4];
    #pragma unroll
    for (int t = 0; t < 13; ++t) { c[t][0] = c[t][1] = c[t][2] = c[t][3] = 0.f; }

    const int NIT = K / 32;
    gemm_stage(Wh, K, Xp, oc0, nh, 0, 0, sWb, sXb, tid);
    gemm_stage(Wh, K, Xp, oc0, nh, 1, 1, sWb, sXb, tid);

    for (int it = 0; it < NIT; ++it) {
        if (it + 2 < NIT) {
            gemm_stage(Wh, K, Xp, oc0, nh, it + 2, (it + 2) % NBUF, sWb, sXb, tid);
            CP_WAIT(2);
        } else if (it + 1 < NIT) {
            CP_WAIT(1);
        } else {
            CP_WAIT(0);
        }
        __syncthreads();
        const int buf = it % NBUF;
        const uint32_t* cW = sW32 + buf * 128 * WST;
        const uint32_t* cX = sX32 + buf * 16 * XST;
        #pragma unroll
        for (int s = 0; s < 2; ++s) {
            uint32_t a0 = cW[(ob + g) * WST + 8 * s + q];
            uint32_t a1 = cW[(ob + g + 8) * WST + 8 * s + q];
            uint32_t a2 = cW[(ob + g) * WST + 8 * s + q + 4];
            uint32_t a3 = cW[(ob + g + 8) * WST + 8 * s + q + 4];
            #pragma unroll
            for (int t = 0; t < 13; ++t) {
                int n = t * 8 + g;
                mma16(c[t], a0, a1, a2, a3,
                      cX[(8 * s + q) * XST + n], cX[(8 * s + q + 4) * XST + n]);
            }
        }
        __syncthreads();
    }

    int r1 = oc0 + ob + g, r2 = r1 + 8;
    if (MODE == 1) {
        float bb1 = g_bproj[r1], bb2 = g_bproj[r2];
        float* Yb = Yout + (size_t)b * DIM * NPIX;
        #pragma unroll
        for (int t = 0; t < 13; ++t) {
            int n0 = nh * 104 + t * 8 + 2 * q;
            if (n0 < NPIX) {
                *(float2*)(Yb + (size_t)r1 * NPIX + n0) = make_float2(c[t][0] + bb1, c[t][1] + bb1);
                *(float2*)(Yb + (size_t)r2 * NPIX + n0) = make_float2(c[t][2] + bb2, c[t][3] + bb2);
            }
        }
    } else {
        float bb1 = g_bqkv[r1], bb2 = g_bqkv[r2];
        if (oc0 < 512) {
            __half* hb = (__half*)((oc0 < 256 ? g_qp32 : g_kp32) + (size_t)b * 128 * 208);
            int cl1 = r1 & 255, cl2 = cl1 + 8;
            #pragma unroll
            for (int t = 0; t < 13; ++t) {
                int n0 = nh * 104 + t * 8 + 2 * q;
                if (n0 < NPIX) {
                    hb[((cl1 >> 1) * 208 + n0) * 2 + (cl1 & 1)]     = __float2half_rn(c[t][0] + bb1);
                    hb[((cl1 >> 1) * 208 + n0 + 1) * 2 + (cl1 & 1)] = __float2half_rn(c[t][1] + bb1);
                    hb[((cl2 >> 1) * 208 + n0) * 2 + (cl2 & 1)]     = __float2half_rn(c[t][2] + bb2);
                    hb[((cl2 >> 1) * 208 + n0 + 1) * 2 + (cl2 & 1)] = __float2half_rn(c[t][3] + bb2);
                }
            }
        } else {
            int d1 = r1 - 512, d2 = d1 + 8;
            float* vf = g_vf + (size_t)b * DH * NPIX;
            uint32_t* vp = g_vp32 + (size_t)b * 104 * DH;
            #pragma unroll
            for (int t = 0; t < 13; ++t) {
                int n0 = nh * 104 + t * 8 + 2 * q;
                if (n0 < NPIX) {
                    float v0 = c[t][0] + bb1, v1 = c[t][1] + bb1;
                    float v2 = c[t][2] + bb2, v3 = c[t][3] + bb2;
                    *(float2*)(vf + (size_t)d1 * NPIX + n0) = make_float2(v0, v1);
                    *(float2*)(vf + (size_t)d2 * NPIX + n0) = make_float2(v2, v3);
                    vp[(size_t)(n0 >> 1) * DH + d1] = packh2(v0, v1);
                    vp[(size_t)(n0 >> 1) * DH + d2] = packh2(v2, v3);
                }
            }
        }
    }
}

// ---------------- depthwise 3x3 local-V: 4 channels per CTA ----------------
__global__ __launch_bounds__(256)
void vloc_kernel()
{
    int blk = blockIdx.x;
    int b = blk >> 8, cq = blk & 255;
    int ch0 = cq * 4;
    __shared__ float sp[4][NPIX];
    __shared__ float swv[36];
    __shared__ float sb[4];
    int t = threadIdx.x;
    const float* src = g_vf + (size_t)b * DH * NPIX + (size_t)ch0 * NPIX;
    for (int e = t; e < 4 * NPIX; e += 256) sp[e / NPIX][e % NPIX] = src[e];
    if (t < 36) swv[t] = g_wvl[ch0 * 9 + t];
    if (t < 4)  sb[t] = g_bvl[ch0 + t];
    __syncthreads();
    for (int e = t; e < 4 * NPIX; e += 256) {
        int cl = e / NPIX, p = e % NPIX;
        int i = p / RES, j = p - i * RES;
        float acc = sb[cl];
        const float* wv = swv + cl * 9;
        #pragma unroll
        for (int di = 0; di < 3; ++di) {
            int ii = i + di - 1;
            if (ii < 0 || ii >= RES) continue;
            #pragma unroll
            for (int dj = 0; dj < 3; ++dj) {
                int jj = j + dj - 1;
                if (jj < 0 || jj >= RES) continue;
                acc += sp[cl][ii * RES + jj] * wv[di * 3 + dj];
            }
        }
        int ch = ch0 + cl;
        g_vlh[(((size_t)b * 512 + (ch >> 1)) * NPIX + p) * 2 + (ch & 1)] = __float2half_rn(acc);
    }
}

// ---------------- fused attention (fp16 mma) ----------------
#define ATTN_SMEM ((HEADS * QT * SP) * 4 + (HEADS * QT * PST) * 4)

__global__ __launch_bounds__(512, 1)
void attn_mma(const float* __restrict__ th1_w, const float* __restrict__ th1_b,
              const float* __restrict__ th2_w, const float* __restrict__ th2_b)
{
    extern __shared__ float sS[];                        // [8][16][SP] fp32 logits/probs
    uint32_t* sP = (uint32_t*)(sS + HEADS * QT * SP);    // [8][16][PST] half2-packed P
    __shared__ float sTh1[64], sTh1b[8], sTh2[64], sTh2b[8];

    const int tile = blockIdx.x, b = blockIdx.y;
    const int nq0 = tile * QT;
    const int tid = threadIdx.x, lane = tid & 31, w = tid >> 5;
    const int h = w >> 1, half_ = w & 1, g = lane >> 2, q = lane & 3;

    if (tid < 64) { sTh1[tid] = th1_w[tid]; sTh2[tid] = th2_w[tid]; }
    if (tid < 8)  { sTh1b[tid] = th1_b[tid]; sTh2b[tid] = th2_b[tid]; }

    // ---- S = Q^T K + bias ----
    {
        const uint32_t* qp = g_qp32 + (size_t)b * 128 * 208;
        const uint32_t* kp = g_kp32 + (size_t)b * 128 * 208;
        float c[13][4];
        #pragma unroll
        for (int t = 0; t < 13; ++t) { c[t][0] = c[t][1] = c[t][2] = c[t][3] = 0.f; }
        #pragma unroll
        for (int s = 0; s < 2; ++s) {
            int row  = (h * 16 + 8 * s + q) * 208;
            int row4 = (h * 16 + 8 * s + q + 4) * 208;
            uint32_t a0 = qp[row + nq0 + g];
            uint32_t a1 = qp[row + nq0 + g + 8];
            uint32_t a2 = qp[row4 + nq0 + g];
            uint32_t a3 = qp[row4 + nq0 + g + 8];
            #pragma unroll
            for (int t = 0; t < 13; ++t) {
                int key = (half_ * 13 + t) * 8 + g;
                mma16(c[t], a0, a1, a2, a3, kp[row + key], kp[row4 + key]);
            }
        }
        float* sh = sS + h * QT * SP;
        const float* bh = g_bias + h * NPIX * NPIX;
        #pragma unroll
        for (int t = 0; t < 13; ++t) {
            int m0 = (half_ * 13 + t) * 8 + 2 * q;
            int r1 = nq0 + g, r2 = nq0 + g + 8;
            float v0 = c[t][0], v1 = c[t][1], v2 = c[t][2], v3 = c[t][3];
            if (m0 < NPIX) {
                if (r1 < NPIX) { v0 += bh[r1 * NPIX + m0]; v1 += bh[r1 * NPIX + m0 + 1]; }
                if (r2 < NPIX) { v2 += bh[r2 * NPIX + m0]; v3 += bh[r2 * NPIX + m0 + 1]; }
            } else { v0 = v1 = v2 = v3 = 0.f; }
            sh[g * SP + m0]       = v0;  sh[g * SP + m0 + 1]       = v1;
            sh[(g + 8) * SP + m0] = v2;  sh[(g + 8) * SP + m0 + 1] = v3;
        }
    }
    __syncthreads();

    // ---- talking-heads mix #1 ----
    for (int e = tid; e < QT * NPIX; e += 512) {
        int r = e / NPIX, m = e - r * NPIX;
        float sv[8];
        #pragma unroll
        for (int i = 0; i < 8; ++i) sv[i] = sS[(i * QT + r) * SP + m];
        #pragma unroll
        for (int o = 0; o < 8; ++o) {
            float a = sTh1b[o];
            #pragma unroll
            for (int i = 0; i < 8; ++i) a += sTh1[o * 8 + i] * sv[i];
            sS[(o * QT + r) * SP + m] = a;
        }
    }
    __syncthreads();

    // ---- softmax ----
    for (int rr = 0; rr < 8; ++rr) {
        float* p = sS + (h * QT + half_ * 8 + rr) * SP;
        float mx = -1e30f;
        for (int m = lane; m < NPIX; m += 32) mx = fmaxf(mx, p[m]);
        #pragma unroll
        for (int o = 16; o; o >>= 1) mx = fmaxf(mx, __shfl_xor_sync(~0u, mx, o));
        float s = 0.f;
        for (int m = lane; m < NPIX; m += 32) { float ev = __expf(p[m] - mx); p[m] = ev; s += ev; }
        #pragma unroll
        for (int o = 16; o; o >>= 1) s += __shfl_xor_sync(~0u, s, o);
        float inv = 1.f / s;
        for (int m = lane; m < NPIX; m += 32) p[m] *= inv;
    }
    __syncthreads();

    // ---- talking-heads mix #2 -> packed half2 P ----
    for (int e = tid; e < QT * 104; e += 512) {
        int r = e / 104, mp = e - r * 104;
        if (mp < 98) {
            int m0 = 2 * mp;
            float sv0[8], sv1[8];
            #pragma unroll
            for (int i = 0; i < 8; ++i) {
                sv0[i] = sS[(i * QT + r) * SP + m0];
                sv1[i] = sS[(i * QT + r) * SP + m0 + 1];
            }
            #pragma unroll
            for (int o = 0; o < 8; ++o) {
                float a0 = sTh2b[o], a1 = sTh2b[o];
                #pragma unroll
                for (int i = 0; i < 8; ++i) {
                    a0 += sTh2[o * 8 + i] * sv0[i];
                    a1 += sTh2[o * 8 + i] * sv1[i];
                }
                sP[(o * QT + r) * PST + mp] = packh2(a0, a1);
            }
        } else {
            #pragma unroll
            for (int o = 0; o < 8; ++o) sP[(o * QT + r) * PST + mp] = 0u;
        }
    }
    __syncthreads();

    // ---- out = P @ V, fused +vloc +relu -> half2 xout [chpair][n] ----
    {
        const uint32_t* vp = g_vp32 + (size_t)b * 104 * DH;
        float c2[8][4];
        #pragma unroll
        for (int t = 0; t < 8; ++t) { c2[t][0] = c2[t][1] = c2[t][2] = c2[t][3] = 0.f; }
        #pragma unroll
        for (int j = 0; j < 13; ++j) {
            uint32_t a0 = sP[(h * QT + g) * PST + 8 * j + q];
            uint32_t a1 = sP[(h * QT + g + 8) * PST + 8 * j + q];
            uint32_t a2 = sP[(h * QT + g) * PST + 8 * j + q + 4];
            uint32_t a3 = sP[(h * QT + g + 8) * PST + 8 * j + q + 4];
            const uint32_t* v0 = vp + (size_t)(8 * j + q) * DH;
            const uint32_t* v4 = vp + (size_t)(8 * j + q + 4) * DH;
            #pragma unroll
            for (int t = 0; t < 8; ++t) {
                int ch = h * DV + (half_ * 8 + t) * 8 + g;
                mma16(c2[t], a0, a1, a2, a3, v0[ch], v4[ch]);
            }
        }
        int r1 = nq0 + g, r2 = nq0 + g + 8;
        #pragma unroll
        for (int t = 0; t < 8; ++t) {
            int cp = h * 64 + (half_ * 8 + t) * 4 + q;
            const uint32_t* vl = (const uint32_t*)g_vlh + ((size_t)b * 512 + cp) * NPIX;
            uint32_t* xo = g_xop32 + ((size_t)b * 512 + cp) * NPIX;
            if (r1 < NPIX) {
                uint32_t wv = vl[r1]; __half2 hv = *(__half2*)&wv;
                float u0 = fmaxf(c2[t][0] + __low2float(hv), 0.f);
                float u1 = fmaxf(c2[t][1] + __high2float(hv), 0.f);
                xo[r1] = packh2(u0, u1);
            }
            if (r2 < NPIX) {
                uint32_t wv = vl[r2]; __half2 hv = *(__half2*)&wv;
                float u2 = fmaxf(c2[t][2] + __low2float(hv), 0.f);
                float u3 = fmaxf(c2[t][3] + __high2float(hv), 0.f);
                xo[r2] = packh2(u2, u3);
            }
        }
    }
}

// ---------------- host launch ----------------
extern "C" void kernel_launch(void* const* d_in, const int* in_sizes, int n_in,
                              void* d_out, int out_size)
{
    const float* x        = (const float*)d_in[0];
    const float* q_w      = (const float*)d_in[1];
    const float* q_b      = (const float*)d_in[2];
    const float* q_s      = (const float*)d_in[3];
    const float* q_t      = (const float*)d_in[4];
    const float* k_w      = (const float*)d_in[5];
    const float* k_b      = (const float*)d_in[6];
    const float* k_s      = (const float*)d_in[7];
    const float* k_t      = (const float*)d_in[8];
    const float* v_w      = (const float*)d_in[9];
    const float* v_b      = (const float*)d_in[10];
    const float* v_s      = (const float*)d_in[11];
    const float* v_t      = (const float*)d_in[12];
    const float* vl_w     = (const float*)d_in[13];
    const float* vl_b     = (const float*)d_in[14];
    const float* vl_s     = (const float*)d_in[15];
    const float* vl_t     = (const float*)d_in[16];
    const float* th1_w    = (const float*)d_in[17];
    const float* th1_b    = (const float*)d_in[18];
    const float* th2_w    = (const float*)d_in[19];
    const float* th2_b    = (const float*)d_in[20];
    const float* proj_w   = (const float*)d_in[21];
    const float* proj_b   = (const float*)d_in[22];
    const float* proj_s   = (const float*)d_in[23];
    const float* proj_t   = (const float*)d_in[24];
    const float* bias_seg = (const float*)d_in[25];
    const int*   bias_idx = (const int*)  d_in[26];
    float*       out      = (float*)d_out;

    const int n_off = in_sizes[25] / HEADS;

    cudaFuncSetAttribute(attn_mma, cudaFuncAttributeMaxDynamicSharedMemorySize, ATTN_SMEM);
    cudaFuncSetAttribute(gemm_mma<0>, cudaFuncAttributeMaxDynamicSharedMemorySize, GEMM_SMEM);
    cudaFuncSetAttribute(gemm_mma<1>, cudaFuncAttributeMaxDynamicSharedMemorySize, GEMM_SMEM);

    // 5 launches; attn_mma sits in the profiled (4th) slot this round
    prep_kernel<<<(PREP_TOTAL + 255) / 256, 256>>>(
        x, q_w, q_b, q_s, q_t, k_w, k_b, k_s, k_t, v_w, v_b, v_s, v_t,
        vl_w, vl_b, vl_s, vl_t, proj_w, proj_b, proj_s, proj_t,
        bias_seg, bias_idx, n_off);

    gemm_mma<0><<<dim3(BATCH, OCQKV / 128, 2), 256, GEMM_SMEM>>>(nullptr);

    vloc_kernel<<<BATCH * 256, 256>>>();

    attn_mma<<<dim3(QTILES, BATCH), 512, ATTN_SMEM>>>(th1_w, th1_b, th2_w, th2_b);   // 4th launch

    gemm_mma<1><<<dim3(BATCH, DIM / 128, 2), 256, GEMM_SMEM>>>(out);
}

// round 16
// speedup vs baseline: 1.0792x; 1.0792x over previous
#include <cuda_runtime.h>
#include <cuda_fp16.h>
#include <cstdint>

// ---------------- problem constants ----------------
#define BATCH   128
#define DIM     384
#define RES     14
#define NPIX    196
#define HEADS   8
#define KD      32
#define DV      128
#define DH      1024
#define OCQKV   1536
#define SCALE_ATTN 0.17677669529663687f
#define QT      16
#define QTILES  13
#define SP      208        // S row stride (floats) in attn smem
#define PST     105        // P half2 row stride (words) in attn smem
#define WST     20         // gemm smem W row stride (words)
#define XST     136        // gemm smem X row stride (words), 136 % 32 = 8 -> conflict-free
#define NBUF    3          // gemm pipeline depth
#define GEMM_SMEM ((NBUF * 128 * WST + NBUF * 16 * XST) * 4)

// ---------------- device scratch (16B-aligned for cp.async / vector access) ----------------
__device__ __align__(16) __half   g_wqkv [OCQKV * DIM];
__device__ float    g_bqkv [OCQKV];
__device__ __align__(16) __half   g_wproj[DIM * DH];
__device__ float    g_bproj[DIM];
__device__ float    g_wvl  [DH * 9];
__device__ float    g_bvl  [DH];
__device__ float    g_bias [HEADS * NPIX * NPIX];
__device__ __align__(16) uint32_t g_xp32 [(size_t)BATCH * 192 * NPIX];     // x half2-pairs [b][cpair][n]
__device__ __align__(16) uint32_t g_qp32 [(size_t)BATCH * 128 * 208];      // Q [b][cpair][n(208)]
__device__ __align__(16) uint32_t g_kp32 [(size_t)BATCH * 128 * 208];      // K [b][cpair][n(208)]
__device__ __align__(16) uint32_t g_vp32 [(size_t)BATCH * 104 * DH];       // V [b][mpair(104)][ch]
__device__ __align__(16) float    g_vf   [(size_t)BATCH * DH * NPIX];      // V float (vloc input)
__device__ __align__(16) __half   g_vlh  [(size_t)BATCH * 512 * NPIX * 2]; // vloc half paired [b][chpair][n][2]
__device__ __align__(16) uint32_t g_xop32[(size_t)BATCH * 512 * NPIX];     // xout half2 [b][chpair][n]

// ---------------- helpers ----------------
__device__ __forceinline__ uint32_t packh2(float lo, float hi) {
    __half2 h = __floats2half2_rn(lo, hi);
    return *(uint32_t*)&h;
}
__device__ __forceinline__ void mma16(float* c, uint32_t a0, uint32_t a1, uint32_t a2, uint32_t a3,
                                      uint32_t b0, uint32_t b1) {
    asm volatile(
        "mma.sync.aligned.m16n8k16.row.col.f32.f16.f16.f32 "
        "{%0,%1,%2,%3},{%4,%5,%6,%7},{%8,%9},{%0,%1,%2,%3};"
        : "+f"(c[0]), "+f"(c[1]), "+f"(c[2]), "+f"(c[3])
        : "r"(a0), "r"(a1), "r"(a2), "r"(a3), "r"(b0), "r"(b1));
}
__device__ __forceinline__ void cp16(uint32_t smem_dst, const void* gsrc) {
    asm volatile("cp.async.cg.shared.global [%0], [%1], 16;" :: "r"(smem_dst), "l"(gsrc));
}
#define CP_COMMIT()  asm volatile("cp.async.commit_group;")
#define CP_WAIT(n)   asm volatile("cp.async.wait_group %0;" :: "n"(n))

// ---------------- unified prep kernel (fold + bias + x-prep + pad) ----------------
#define SEG_A (OCQKV * DIM)                 // fold qkv weights
#define SEG_B (DIM * DH)                    // fold proj weights
#define SEG_C (DH * 9)                      // fold vl weights
#define SEG_D (HEADS * NPIX * NPIX)         // bias expand
#define SEG_E (BATCH * 192 * NPIX)          // x half2 pack
#define SEG_F (BATCH * 9216)                // pad zero q/k/v
#define PREP_TOTAL (SEG_A + SEG_B + SEG_C + SEG_D + SEG_E + SEG_F)

__global__ void prep_kernel(
    const float* __restrict__ x,
    const float* __restrict__ q_w, const float* __restrict__ q_b,
    const float* __restrict__ q_s, const float* __restrict__ q_t,
    const float* __restrict__ k_w, const float* __restrict__ k_b,
    const float* __restrict__ k_s, const float* __restrict__ k_t,
    const float* __restrict__ v_w, const float* __restrict__ v_b,
    const float* __restrict__ v_s, const float* __restrict__ v_t,
    const float* __restrict__ vl_w, const float* __restrict__ vl_b,
    const float* __restrict__ vl_s, const float* __restrict__ vl_t,
    const float* __restrict__ p_w, const float* __restrict__ p_b,
    const float* __restrict__ p_s, const float* __restrict__ p_t,
    const float* __restrict__ bias_seg, const int* __restrict__ bias_idxs,
    int n_off)
{
    int idx = blockIdx.x * blockDim.x + threadIdx.x;
    if (idx < SEG_A) {
        int oc = idx / DIM, c = idx - oc * DIM;
        float w, s;
        if (oc < 256) {
            w = q_w[oc * DIM + c]; s = q_s[oc] * SCALE_ATTN;
            if (c == 0) g_bqkv[oc] = (q_b[oc] * q_s[oc] + q_t[oc]) * SCALE_ATTN;
        } else if (oc < 512) {
            int o = oc - 256;
            w = k_w[o * DIM + c]; s = k_s[o];
            if (c == 0) g_bqkv[oc] = k_b[o] * k_s[o] + k_t[o];
        } else {
            int o = oc - 512;
            w = v_w[o * DIM + c]; s = v_s[o];
            if (c == 0) g_bqkv[oc] = v_b[o] * v_s[o] + v_t[o];
        }
        g_wqkv[idx] = __float2half_rn(w * s);
        return;
    }
    idx -= SEG_A;
    if (idx < SEG_B) {
        int oc = idx / DH;
        g_wproj[idx] = __float2half_rn(p_w[idx] * p_s[oc]);
        if ((idx - oc * DH) == 0) g_bproj[oc] = p_b[oc] * p_s[oc] + p_t[oc];
        return;
    }
    idx -= SEG_B;
    if (idx < SEG_C) {
        int ch = idx / 9;
        g_wvl[idx] = vl_w[idx] * vl_s[ch];
        if (idx == ch * 9) g_bvl[ch] = vl_b[ch] * vl_s[ch] + vl_t[ch];
        return;
    }
    idx -= SEG_C;
    if (idx < SEG_D) {
        int h = idx / (NPIX * NPIX), nm = idx - h * (NPIX * NPIX);
        g_bias[idx] = bias_seg[h * n_off + bias_idxs[nm]];
        return;
    }
    idx -= SEG_D;
    if (idx < SEG_E) {
        int n = idx % NPIX, cp = (idx / NPIX) % 192, b = idx / (NPIX * 192);
        const float* xr = x + ((size_t)b * DIM + 2 * cp) * NPIX + n;
        g_xp32[idx] = packh2(xr[0], xr[NPIX]);
        return;
    }
    idx -= SEG_E;
    if (idx < SEG_F) {
        int b = idx / 9216, i = idx % 9216;
        if (i < 1536) {
            int cp = i / 12, ni = i % 12;
            g_qp32[((size_t)b * 128 + cp) * 208 + 196 + ni] = 0u;
        } else if (i < 3072) {
            int r = i - 1536, cp = r / 12, ni = r % 12;
            g_kp32[((size_t)b * 128 + cp) * 208 + 196 + ni] = 0u;
        } else {
            int r = i - 3072;
            int mp = 98 + r / DH, d = r % DH;
            g_vp32[(size_t)b * 104 * DH + (size_t)mp * DH + d] = 0u;
        }
    }
}

// ---------------- fp16 GEMM: 256-thread CTA, tile 128oc x 104n, 2 CTAs/SM, 3-stage ----------------
__device__ __forceinline__ void gemm_stage(const __half* W, int ldw, const uint32_t* Xp,
                                           int oc0, int nh, int it, int buf,
                                           uint32_t sWb, uint32_t sXb, int tid)
{
    int k0 = it * 32;
    #pragma unroll
    for (int e = tid; e < 512; e += 256) {
        int oc = e >> 2, cc = e & 3;
        cp16(sWb + (((buf * 128) + oc) * WST + cc * 4) * 4,
             W + (size_t)(oc0 + oc) * ldw + k0 + cc * 8);
    }
    int cnt = nh ? 23 : 26;                 // nh1: cols 92..103 are global pad (prezeroed in smem)
    for (int e = tid; e < 16 * cnt; e += 256) {
        int pr = e / cnt, cc = e - pr * cnt;
        cp16(sXb + ((buf * 16 + pr) * XST + cc * 4) * 4,
             Xp + (size_t)(it * 16 + pr) * NPIX + nh * 104 + cc * 4);
    }
    CP_COMMIT();
}

// MODE 0: QKV (K=DIM, X=g_xp32), MODE 1: proj (K=DH, X=g_xop32, Y=d_out)
template<int MODE>
__global__ __launch_bounds__(256, 2)
void gemm_mma(float* __restrict__ Yout)
{
    extern __shared__ __align__(16) uint32_t dsm[];
    uint32_t* sW32 = dsm;                        // [NBUF][128][WST]
    uint32_t* sX32 = dsm + NBUF * 128 * WST;     // [NBUF][16][XST]

    const int K = (MODE == 0) ? DIM : DH;
    const __half* Wh = (MODE == 0) ? g_wqkv : g_wproj;
    const int b = blockIdx.x, oc0 = blockIdx.y * 128, nh = blockIdx.z;
    const uint32_t* Xp = ((MODE == 0) ? g_xp32 : g_xop32) + (size_t)b * (K / 2) * NPIX;

    const int tid = threadIdx.x, lane = tid & 31, w = tid >> 5;
    const int g = lane >> 2, q = lane & 3;
    const int ob = w * 16;

    if (nh) {
        for (int e = tid; e < NBUF * 16 * 12; e += 256) {
            int buf = e / 192, rem = e % 192;
            sX32[(buf * 16 + rem / 12) * XST + 92 + rem % 12] = 0u;
        }
        __syncthreads();
    }

    uint32_t sWb = (uint32_t)__cvta_generic_to_shared(sW32);
    uint32_t sXb = (uint32_t)__cvta_generic_to_shared(sX32);

    float c[13][4];
    #pragma unroll
    for (int t = 0; t < 13; ++t) { c[t][0] = c[t][1] = c[t][2] = c[t][3] = 0.f; }

    const int NIT = K / 32;
    gemm_stage(Wh, K, Xp, oc0, nh, 0, 0, sWb, sXb, tid);
    gemm_stage(Wh, K, Xp, oc0, nh, 1, 1, sWb, sXb, tid);

    for (int it = 0; it < NIT; ++it) {
        if (it + 2 < NIT) {
            gemm_stage(Wh, K, Xp, oc0, nh, it + 2, (it + 2) % NBUF, sWb, sXb, tid);
            CP_WAIT(2);
        } else if (it + 1 < NIT) {
            CP_WAIT(1);
        } else {
            CP_WAIT(0);
        }
        __syncthreads();
        const int buf = it % NBUF;
        const uint32_t* cW = sW32 + buf * 128 * WST;
        const uint32_t* cX = sX32 + buf * 16 * XST;
        #pragma unroll
        for (int s = 0; s < 2; ++s) {
            uint32_t a0 = cW[(ob + g) * WST + 8 * s + q];
            uint32_t a1 = cW[(ob + g + 8) * WST + 8 * s + q];
            uint32_t a2 = cW[(ob + g) * WST + 8 * s + q + 4];
            uint32_t a3 = cW[(ob + g + 8) * WST + 8 * s + q + 4];
            #pragma unroll
            for (int t = 0; t < 13; ++t) {
                int n = t * 8 + g;
                mma16(c[t], a0, a1, a2, a3,
                      cX[(8 * s + q) * XST + n], cX[(8 * s + q + 4) * XST + n]);
            }
        }
        __syncthreads();
    }

    int r1 = oc0 + ob + g, r2 = r1 + 8;
    if (MODE == 1) {
        float bb1 = g_bproj[r1], bb2 = g_bproj[r2];
        float* Yb = Yout + (size_t)b * DIM * NPIX;
        #pragma unroll
        for (int t = 0; t < 13; ++t) {
            int n0 = nh * 104 + t * 8 + 2 * q;
            if (n0 < NPIX) {
                *(float2*)(Yb + (size_t)r1 * NPIX + n0) = make_float2(c[t][0] + bb1, c[t][1] + bb1);
                *(float2*)(Yb + (size_t)r2 * NPIX + n0) = make_float2(c[t][2] + bb2, c[t][3] + bb2);
            }
        }
    } else {
        float bb1 = g_bqkv[r1], bb2 = g_bqkv[r2];
        if (oc0 < 512) {
            __half* hb = (__half*)((oc0 < 256 ? g_qp32 : g_kp32) + (size_t)b * 128 * 208);
            int cl1 = r1 & 255, cl2 = cl1 + 8;
            #pragma unroll
            for (int t = 0; t < 13; ++t) {
                int n0 = nh * 104 + t * 8 + 2 * q;
                if (n0 < NPIX) {
                    hb[((cl1 >> 1) * 208 + n0) * 2 + (cl1 & 1)]     = __float2half_rn(c[t][0] + bb1);
                    hb[((cl1 >> 1) * 208 + n0 + 1) * 2 + (cl1 & 1)] = __float2half_rn(c[t][1] + bb1);
                    hb[((cl2 >> 1) * 208 + n0) * 2 + (cl2 & 1)]     = __float2half_rn(c[t][2] + bb2);
                    hb[((cl2 >> 1) * 208 + n0 + 1) * 2 + (cl2 & 1)] = __float2half_rn(c[t][3] + bb2);
                }
            }
        } else {
            int d1 = r1 - 512, d2 = d1 + 8;
            float* vf = g_vf + (size_t)b * DH * NPIX;
            uint32_t* vp = g_vp32 + (size_t)b * 104 * DH;
            #pragma unroll
            for (int t = 0; t < 13; ++t) {
                int n0 = nh * 104 + t * 8 + 2 * q;
                if (n0 < NPIX) {
                    float v0 = c[t][0] + bb1, v1 = c[t][1] + bb1;
                    float v2 = c[t][2] + bb2, v3 = c[t][3] + bb2;
                    *(float2*)(vf + (size_t)d1 * NPIX + n0) = make_float2(v0, v1);
                    *(float2*)(vf + (size_t)d2 * NPIX + n0) = make_float2(v2, v3);
                    vp[(size_t)(n0 >> 1) * DH + d1] = packh2(v0, v1);
                    vp[(size_t)(n0 >> 1) * DH + d2] = packh2(v2, v3);
                }
            }
        }
    }
}

// ---------------- depthwise 3x3 local-V: 4 channels per CTA ----------------
__global__ __launch_bounds__(256)
void vloc_kernel()
{
    int blk = blockIdx.x;
    int b = blk >> 8, cq = blk & 255;
    int ch0 = cq * 4;
    __shared__ float sp[4][NPIX];
    __shared__ float swv[36];
    __shared__ float sb[4];
    int t = threadIdx.x;
    const float* src = g_vf + (size_t)b * DH * NPIX + (size_t)ch0 * NPIX;
    for (int e = t; e < 4 * NPIX; e += 256) sp[e / NPIX][e % NPIX] = src[e];
    if (t < 36) swv[t] = g_wvl[ch0 * 9 + t];
    if (t < 4)  sb[t] = g_bvl[ch0 + t];
    __syncthreads();
    for (int e = t; e < 4 * NPIX; e += 256) {
        int cl = e / NPIX, p = e % NPIX;
        int i = p / RES, j = p - i * RES;
        float acc = sb[cl];
        const float* wv = swv + cl * 9;
        #pragma unroll
        for (int di = 0; di < 3; ++di) {
            int ii = i + di - 1;
            if (ii < 0 || ii >= RES) continue;
            #pragma unroll
            for (int dj = 0; dj < 3; ++dj) {
                int jj = j + dj - 1;
                if (jj < 0 || jj >= RES) continue;
                acc += sp[cl][ii * RES + jj] * wv[di * 3 + dj];
            }
        }
        int ch = ch0 + cl;
        g_vlh[(((size_t)b * 512 + (ch >> 1)) * NPIX + p) * 2 + (ch & 1)] = __float2half_rn(acc);
    }
}

// ---------------- fused attention (fp16 mma, ILP-optimized scalar phases) ----------------
#define ATTN_SMEM ((HEADS * QT * SP) * 4 + (HEADS * QT * PST) * 4)

__global__ __launch_bounds__(512, 1)
void attn_mma(const float* __restrict__ th1_w, const float* __restrict__ th1_b,
              const float* __restrict__ th2_w, const float* __restrict__ th2_b)
{
    extern __shared__ float sS[];                        // [8][16][SP] fp32 logits/probs
    uint32_t* sP = (uint32_t*)(sS + HEADS * QT * SP);    // [8][16][PST] half2-packed P
    __shared__ float sTh1[64], sTh1b[8], sTh2[64], sTh2b[8];
    __shared__ float sInv[HEADS * QT];

    const int tile = blockIdx.x, b = blockIdx.y;
    const int nq0 = tile * QT;
    const int tid = threadIdx.x, lane = tid & 31, w = tid >> 5;
    const int h = w >> 1, half_ = w & 1, g = lane >> 2, q = lane & 3;

    if (tid < 64) { sTh1[tid] = th1_w[tid]; sTh2[tid] = th2_w[tid]; }
    if (tid < 8)  { sTh1b[tid] = th1_b[tid]; sTh2b[tid] = th2_b[tid]; }

    // ---- S = Q^T K + bias ----
    {
        const uint32_t* qp = g_qp32 + (size_t)b * 128 * 208;
        const uint32_t* kp = g_kp32 + (size_t)b * 128 * 208;
        float c[13][4];
        #pragma unroll
        for (int t = 0; t < 13; ++t) { c[t][0] = c[t][1] = c[t][2] = c[t][3] = 0.f; }
        #pragma unroll
        for (int s = 0; s < 2; ++s) {
            int row  = (h * 16 + 8 * s + q) * 208;
            int row4 = (h * 16 + 8 * s + q + 4) * 208;
            uint32_t a0 = qp[row + nq0 + g];
            uint32_t a1 = qp[row + nq0 + g + 8];
            uint32_t a2 = qp[row4 + nq0 + g];
            uint32_t a3 = qp[row4 + nq0 + g + 8];
            #pragma unroll
            for (int t = 0; t < 13; ++t) {
                int key = (half_ * 13 + t) * 8 + g;
                mma16(c[t], a0, a1, a2, a3, kp[row + key], kp[row4 + key]);
            }
        }
        float* sh = sS + h * QT * SP;
        const float* bh = g_bias + h * NPIX * NPIX;
        #pragma unroll
        for (int t = 0; t < 13; ++t) {
            int m0 = (half_ * 13 + t) * 8 + 2 * q;
            int r1 = nq0 + g, r2 = nq0 + g + 8;
            float v0 = c[t][0], v1 = c[t][1], v2 = c[t][2], v3 = c[t][3];
            if (m0 < NPIX) {
                if (r1 < NPIX) { v0 += bh[r1 * NPIX + m0]; v1 += bh[r1 * NPIX + m0 + 1]; }
                if (r2 < NPIX) { v2 += bh[r2 * NPIX + m0]; v3 += bh[r2 * NPIX + m0 + 1]; }
            } else { v0 = v1 = v2 = v3 = 0.f; }
            sh[g * SP + m0]       = v0;  sh[g * SP + m0 + 1]       = v1;
            sh[(g + 8) * SP + m0] = v2;  sh[(g + 8) * SP + m0 + 1] = v3;
        }
    }
    __syncthreads();

    // ---- talking-heads mix #1 (float2 vectorized) ----
    for (int e = tid; e < QT * 98; e += 512) {
        int r = e / 98, mp = e - r * 98;
        int m0 = 2 * mp;
        float2 sv[8];
        #pragma unroll
        for (int i = 0; i < 8; ++i) sv[i] = *(float2*)&sS[(i * QT + r) * SP + m0];
        #pragma unroll
        for (int o = 0; o < 8; ++o) {
            float a0 = sTh1b[o], a1 = sTh1b[o];
            #pragma unroll
            for (int i = 0; i < 8; ++i) {
                a0 += sTh1[o * 8 + i] * sv[i].x;
                a1 += sTh1[o * 8 + i] * sv[i].y;
            }
            *(float2*)&sS[(o * QT + r) * SP + m0] = make_float2(a0, a1);
        }
    }
    __syncthreads();

    // ---- softmax: warp handles its 8 rows IN PARALLEL (reg arrays, interleaved shfl) ----
    {
        float* pb = sS + (h * QT + half_ * 8) * SP;
        float mx[8], sm[8];
        #pragma unroll
        for (int r = 0; r < 8; ++r) mx[r] = -1e30f;
        for (int m = lane; m < NPIX; m += 32) {
            #pragma unroll
            for (int r = 0; r < 8; ++r) mx[r] = fmaxf(mx[r], pb[r * SP + m]);
        }
        #pragma unroll
        for (int o = 16; o; o >>= 1) {
            #pragma unroll
            for (int r = 0; r < 8; ++r) mx[r] = fmaxf(mx[r], __shfl_xor_sync(~0u, mx[r], o));
        }
        #pragma unroll
        for (int r = 0; r < 8; ++r) sm[r] = 0.f;
        for (int m = lane; m < NPIX; m += 32) {
            #pragma unroll
            for (int r = 0; r < 8; ++r) {
                float ev = __expf(pb[r * SP + m] - mx[r]);
                pb[r * SP + m] = ev;
                sm[r] += ev;
            }
        }
        #pragma unroll
        for (int o = 16; o; o >>= 1) {
            #pragma unroll
            for (int r = 0; r < 8; ++r) sm[r] += __shfl_xor_sync(~0u, sm[r], o);
        }
        if (lane == 0) {
            #pragma unroll
            for (int r = 0; r < 8; ++r) sInv[h * QT + half_ * 8 + r] = 1.f / sm[r];
        }
    }
    __syncthreads();

    // ---- talking-heads mix #2 (normalize folded in) -> packed half2 P ----
    for (int e = tid; e < QT * 104; e += 512) {
        int r = e / 104, mp = e - r * 104;
        if (mp < 98) {
            int m0 = 2 * mp;
            float sv0[8], sv1[8];
            #pragma unroll
            for (int i = 0; i < 8; ++i) {
                float inv = sInv[i * QT + r];
                sv0[i] = sS[(i * QT + r) * SP + m0] * inv;
                sv1[i] = sS[(i * QT + r) * SP + m0 + 1] * inv;
            }
            #pragma unroll
            for (int o = 0; o < 8; ++o) {
                float a0 = sTh2b[o], a1 = sTh2b[o];
                #pragma unroll
                for (int i = 0; i < 8; ++i) {
                    a0 += sTh2[o * 8 + i] * sv0[i];
                    a1 += sTh2[o * 8 + i] * sv1[i];
                }
                sP[(o * QT + r) * PST + mp] = packh2(a0, a1);
            }
        } else {
            #pragma unroll
            for (int o = 0; o < 8; ++o) sP[(o * QT + r) * PST + mp] = 0u;
        }
    }
    __syncthreads();

    // ---- out = P @ V, fused +vloc +relu -> half2 xout [chpair][n] ----
    {
        const uint32_t* vp = g_vp32 + (size_t)b * 104 * DH;
        float c2[8][4];
        #pragma unroll
        for (int t = 0; t < 8; ++t) { c2[t][0] = c2[t][1] = c2[t][2] = c2[t][3] = 0.f; }
        #pragma unroll
        for (int j = 0; j < 13; ++j) {
            uint32_t a0 = sP[(h * QT + g) * PST + 8 * j + q];
            uint32_t a1 = sP[(h * QT + g + 8) * PST + 8 * j + q];
            uint32_t a2 = sP[(h * QT + g) * PST + 8 * j + q + 4];
            uint32_t a3 = sP[(h * QT + g + 8) * PST + 8 * j + q + 4];
            const uint32_t* v0 = vp + (size_t)(8 * j + q) * DH;
            const uint32_t* v4 = vp + (size_t)(8 * j + q + 4) * DH;
            #pragma unroll
            for (int t = 0; t < 8; ++t) {
                int ch = h * DV + (half_ * 8 + t) * 8 + g;
                mma16(c2[t], a0, a1, a2, a3, v0[ch], v4[ch]);
            }
        }
        int r1 = nq0 + g, r2 = nq0 + g + 8;
        #pragma unroll
        for (int t = 0; t < 8; ++t) {
            int cp = h * 64 + (half_ * 8 + t) * 4 + q;
            const uint32_t* vl = (const uint32_t*)g_vlh + ((size_t)b * 512 + cp) * NPIX;
            uint32_t* xo = g_xop32 + ((size_t)b * 512 + cp) * NPIX;
            if (r1 < NPIX) {
                uint32_t wv = vl[r1]; __half2 hv = *(__half2*)&wv;
                float u0 = fmaxf(c2[t][0] + __low2float(hv), 0.f);
                float u1 = fmaxf(c2[t][1] + __high2float(hv), 0.f);
                xo[r1] = packh2(u0, u1);
            }
            if (r2 < NPIX) {
                uint32_t wv = vl[r2]; __half2 hv = *(__half2*)&wv;
                float u2 = fmaxf(c2[t][2] + __low2float(hv), 0.f);
                float u3 = fmaxf(c2[t][3] + __high2float(hv), 0.f);
                xo[r2] = packh2(u2, u3);
            }
        }
    }
}

// ---------------- host launch ----------------
extern "C" void kernel_launch(void* const* d_in, const int* in_sizes, int n_in,
                              void* d_out, int out_size)
{
    const float* x        = (const float*)d_in[0];
    const float* q_w      = (const float*)d_in[1];
    const float* q_b      = (const float*)d_in[2];
    const float* q_s      = (const float*)d_in[3];
    const float* q_t      = (const float*)d_in[4];
    const float* k_w      = (const float*)d_in[5];
    const float* k_b      = (const float*)d_in[6];
    const float* k_s      = (const float*)d_in[7];
    const float* k_t      = (const float*)d_in[8];
    const float* v_w      = (const float*)d_in[9];
    const float* v_b      = (const float*)d_in[10];
    const float* v_s      = (const float*)d_in[11];
    const float* v_t      = (const float*)d_in[12];
    const float* vl_w     = (const float*)d_in[13];
    const float* vl_b     = (const float*)d_in[14];
    const float* vl_s     = (const float*)d_in[15];
    const float* vl_t     = (const float*)d_in[16];
    const float* th1_w    = (const float*)d_in[17];
    const float* th1_b    = (const float*)d_in[18];
    const float* th2_w    = (const float*)d_in[19];
    const float* th2_b    = (const float*)d_in[20];
    const float* proj_w   = (const float*)d_in[21];
    const float* proj_b   = (const float*)d_in[22];
    const float* proj_s   = (const float*)d_in[23];
    const float* proj_t   = (const float*)d_in[24];
    const float* bias_seg = (const float*)d_in[25];
    const int*   bias_idx = (const int*)  d_in[26];
    float*       out      = (float*)d_out;

    const int n_off = in_sizes[25] / HEADS;

    cudaFuncSetAttribute(attn_mma, cudaFuncAttributeMaxDynamicSharedMemorySize, ATTN_SMEM);
    cudaFuncSetAttribute(gemm_mma<0>, cudaFuncAttributeMaxDynamicSharedMemorySize, GEMM_SMEM);
    cudaFuncSetAttribute(gemm_mma<1>, cudaFuncAttributeMaxDynamicSharedMemorySize, GEMM_SMEM);

    // 5 launches; attn_mma in the profiled (4th) slot
    prep_kernel<<<(PREP_TOTAL + 255) / 256, 256>>>(
        x, q_w, q_b, q_s, q_t, k_w, k_b, k_s, k_t, v_w, v_b, v_s, v_t,
        vl_w, vl_b, vl_s, vl_t, proj_w, proj_b, proj_s, proj_t,
        bias_seg, bias_idx, n_off);

    gemm_mma<0><<<dim3(BATCH, OCQKV / 128, 2), 256, GEMM_SMEM>>>(nullptr);

    vloc_kernel<<<BATCH * 256, 256>>>();

    attn_mma<<<dim3(QTILES, BATCH), 512, ATTN_SMEM>>>(th1_w, th1_b, th2_w, th2_b);   // 4th launch

    gemm_mma<1><<<dim3(BATCH, DIM / 128, 2), 256, GEMM_SMEM>>>(out);
}